// round 13
// baseline (speedup 1.0000x reference)
#include <cuda_runtime.h>
#include <cuda_fp16.h>
#include <cstdint>

// DeformableFusionAcrossFocus R12: weights-in-registers partition.
// Warp = (oc quarter, site quarter): holds 12 WF uint4 in regs across the whole
// main loop; per site loads 8 prepacked fp16 X B-frags from smem. Stage-1 makes
// both n-halves in-warp -> stage-2 A-frag assembled without any exchange.
// Numerics identical to R10 (rel_err 6.039e-4).

#define HW 9216
#define NWF 1792     // 14 oc-groups * 4 ks * 32 lanes

// ---- smem byte layout ----
#define SM_WF    0        // weight A-frags = 28672
#define SM_XBF   28672    // prepacked X B-frags [site16][t2][ks4][lane32] uint2 = 32768
#define SM_SCR   61440    // X f32 staging 70656B; reused as STG2 (65536B)
#define SM_ZOF   132096   // per-site offset rows: 16 * 384 floats = 24576
#define SM_CB    156672   // coeff tables: W0[768] W1[768] S[768] = 9216
#define SM_BD    165888   // 64 floats
#define SM_BO    166144   // 6 floats (+pad)
#define SMEM_TOTAL 166176

__device__ uint4 g_WF[NWF];

__device__ __forceinline__ void mma16816(float& d0, float& d1, float& d2, float& d3,
                                         uint4 a, uint2 b) {
    asm volatile(
        "mma.sync.aligned.m16n8k16.row.col.f32.f16.f16.f32 "
        "{%0,%1,%2,%3}, {%4,%5,%6,%7}, {%8,%9}, {%0,%1,%2,%3};"
        : "+f"(d0), "+f"(d1), "+f"(d2), "+f"(d3)
        : "r"(a.x), "r"(a.y), "r"(a.z), "r"(a.w), "r"(b.x), "r"(b.y));
}

__device__ __forceinline__ uint32_t pk16(float vlo, float vhi) {
    uint32_t r;
    asm("cvt.rn.f16x2.f32 %0, %1, %2;" : "=r"(r) : "f"(vhi), "f"(vlo));
    return r;
}
__device__ __forceinline__ float2 h2f2(uint32_t h) {
    __half2 hh = *reinterpret_cast<__half2*>(&h);
    return __half22float2(hh);
}

__device__ __forceinline__ float wval(int m, int c,
                                      const float* __restrict__ w_def,
                                      const float* __restrict__ w_off) {
    if (m < 192) { int kk = m >> 6, o = m & 63; return __ldg(w_def + o * 192 + c * 3 + kk); }
    if (m < 210) { int t = m - 192; int kk = t / 6, j = t - 6 * kk;
                   return __ldg(w_off + j * 192 + c * 3 + kk); }
    return 0.f;
}

// ---------------- prep: build weight A-fragments once ----------------
__global__ void deform_prep_kernel(const float* __restrict__ w_off,
                                   const float* __restrict__ w_def)
{
    int idx = blockIdx.x * blockDim.x + threadIdx.x;
    if (idx >= NWF) return;
    int l = idx & 31, rem = idx >> 5;
    int ks = rem & 3, oc = rem >> 2;
    int qq = l & 3, gg = l >> 2;
    int c0 = ks * 16 + qq * 2;
    int m0 = oc * 16 + gg, m1 = m0 + 8;
    uint32_t a0 = pk16(wval(m0, c0,     w_def, w_off), wval(m0, c0 + 1, w_def, w_off));
    uint32_t a1 = pk16(wval(m1, c0,     w_def, w_off), wval(m1, c0 + 1, w_def, w_off));
    uint32_t a2 = pk16(wval(m0, c0 + 8, w_def, w_off), wval(m0, c0 + 9, w_def, w_off));
    uint32_t a3 = pk16(wval(m1, c0 + 8, w_def, w_off), wval(m1, c0 + 9, w_def, w_off));
    g_WF[(oc * 4 + ks) * 32 + l] = make_uint4(a0, a1, a2, a3);
}

__global__ void __launch_bounds__(512, 1)
deform_hmma10_kernel(const float* __restrict__ x,
                     const float* __restrict__ b_off,
                     const float* __restrict__ b_def,
                     float* __restrict__ out)
{
    extern __shared__ char smem[];
    uint4*  WF   = (uint4*)(smem + SM_WF);
    uint2*  XBF  = (uint2*)(smem + SM_XBF);
    float*  SCR  = (float*)(smem + SM_SCR);
    float*  ZOF  = (float*)(smem + SM_ZOF);
    float*  CBW0 = (float*)(smem + SM_CB);
    float*  CBW1 = CBW0 + 768;
    int*    CBS  = (int*)(CBW1 + 768);
    float*  BD   = (float*)(smem + SM_BD);
    float*  BO   = (float*)(smem + SM_BO);

    const int tid  = threadIdx.x;
    const int wid  = tid >> 5;
    const int lane = tid & 31;
    const int oc   = wid >> 2;       // output-row quarter (o in [oc*16, oc*16+16))
    const int sq   = wid & 3;        // site quarter (sites sq*4 .. sq*4+3)
    const int g    = lane >> 2;
    const int q    = lane & 3;

    const int bid = blockIdx.x;      // 0..1151
    const int b   = bid / 576;
    const int h   = (bid / 6) % 96;
    const int w0  = (bid % 6) * 16;
    const long xbase = (long)b * (64 * 16 * HW) + (long)h * 96 + w0;

    if (tid < 64) BD[tid] = b_def[tid];
    if (tid < 6)  BO[tid] = b_off[tid];

    // ---------------- stage X[c][s][n] -> SCR[c*276 + s*17 + n] ----------------
    {
        const float* xb = x + xbase;
        #pragma unroll 8
        for (int i = tid; i < 16384; i += 512) {
            int s = i & 15, n = (i >> 4) & 15, c = i >> 8;
            SCR[c * 276 + s * 17 + n] = xb[(long)(c * 16 + n) * HW + s];
        }
    }
    // ---------------- weight A-fragments: coalesced copy ----------------
    #pragma unroll 4
    for (int i = tid; i < NWF; i += 512)
        WF[i] = g_WF[i];
    __syncthreads();

    // ---------------- prepack X B-frags (fp16) into XBF ----------------
    // entry (site, t, ks, l=(gg,qq)): {pk(v0,v1), pk(v2,v3)}, c0=ks*16+qq*2, nn=t*8+gg
    #pragma unroll
    for (int it = 0; it < 8; it++) {
        int idx = tid + it * 512;
        int l = idx & 31, ks = (idx >> 5) & 3, t = (idx >> 7) & 1, site = idx >> 8;
        int c0 = ks * 16 + (l & 3) * 2;
        int nn = t * 8 + (l >> 2);
        const float* base = SCR + site * 17 + nn;
        float v0 = base[(c0    ) * 276];
        float v1 = base[(c0 + 1) * 276];
        float v2 = base[(c0 + 8) * 276];
        float v3 = base[(c0 + 9) * 276];
        XBF[idx] = make_uint2(pk16(v0, v1), pk16(v2, v3));
    }
    __syncthreads();   // XBF ready; SCR free for STG2

    // ---------------- offsets: warp w computes site w (ocg 12,13) -> ZOF ----------------
    {
        const int site = wid;
        uint2 bo[2][4];
        #pragma unroll
        for (int t = 0; t < 2; t++)
            #pragma unroll
            for (int ks = 0; ks < 4; ks++)
                bo[t][ks] = XBF[((site * 2 + t) * 4 + ks) * 32 + lane];
        float* zoff = ZOF + site * 384;   // rows 0..17, stride 20
        #pragma unroll
        for (int oo = 0; oo < 2; oo++) {
            const int ocg = 12 + oo;
            float dA0 = 0.f, dA1 = 0.f, dA2 = 0.f, dA3 = 0.f;
            float dB0 = 0.f, dB1 = 0.f, dB2 = 0.f, dB3 = 0.f;
            #pragma unroll
            for (int ks = 0; ks < 4; ks++) {
                uint4 a = WF[(ocg * 4 + ks) * 32 + lane];
                mma16816(dA0, dA1, dA2, dA3, a, bo[0][ks]);
                mma16816(dB0, dB1, dB2, dB3, a, bo[1][ks]);
            }
            int r0 = oo * 16 + g;
            if (r0 < 18) {
                *(float2*)(zoff + r0 * 20 + q * 2)     = make_float2(dA0, dA1);
                *(float2*)(zoff + r0 * 20 + 8 + q * 2) = make_float2(dB0, dB1);
            }
            int r1 = r0 + 8;
            if (r1 < 18) {
                *(float2*)(zoff + r1 * 20 + q * 2)     = make_float2(dA2, dA3);
                *(float2*)(zoff + r1 * 20 + 8 + q * 2) = make_float2(dB2, dB3);
            }
        }
    }
    __syncthreads();

    // ---------------- coefficients -> CB tables (256 threads) ----------------
    if (tid < 256) {
        int cs = tid >> 4, cn = tid & 15;
        const float* zf = ZOF + cs * 384;
        float offv[6];
        #pragma unroll
        for (int j = 0; j < 6; j++) {
            float v = BO[j];
            #pragma unroll
            for (int kk = 0; kk < 3; kk++) {
                int np = cn - 1 + kk;
                if (np >= 0 && np < 16) v += zf[(kk * 6 + j) * 20 + np];
            }
            offv[j] = v;
        }
        #pragma unroll
        for (int k = 0; k < 3; k++) {
            float px  = (float)(cn - 1 + k) + offv[2 * k + 1];
            float x0f = floorf(px);
            float fx  = px - x0f;
            int x0i = (int)x0f, x1i = x0i + 1;
            float wy = fmaxf(0.f, 1.f - fabsf(offv[2 * k]));
            float W0 = (x0i >= 0 && x0i < 16) ? (1.f - fx) * wy : 0.f;
            float W1 = (x1i >= 0 && x1i < 16) ? fx * wy : 0.f;
            int s0 = min(max(x0i, 0), 15);
            int s1 = min(max(x1i, 0), 15);
            int ci = cs * 48 + k * 16 + cn;
            CBW0[ci] = W0; CBW1[ci] = W1; CBS[ci] = (s0 << 4) | s1;
        }
    }
    __syncthreads();

    // ---------------- load this warp's 12 weight fragments into registers ----------------
    uint4 wf[12];
    #pragma unroll
    for (int k3 = 0; k3 < 3; k3++)
        #pragma unroll
        for (int ks = 0; ks < 4; ks++)
            wf[k3 * 4 + ks] = WF[((k3 * 4 + oc) * 4 + ks) * 32 + lane];

    const float bd0 = BD[oc * 16 + g];
    const float bd1 = BD[oc * 16 + g + 8];
    float* STG2 = SCR;

    // ---------------- main: per site (4), per k3: stage-1 + stage-2 in-warp ----------------
    #pragma unroll 1
    for (int s4 = 0; s4 < 4; s4++) {
        const int site = sq * 4 + s4;
        uint2 bh[2][4];
        #pragma unroll
        for (int t = 0; t < 2; t++)
            #pragma unroll
            for (int ks = 0; ks < 4; ks++)
                bh[t][ks] = XBF[((site * 2 + t) * 4 + ks) * 32 + lane];

        float oa0[4] = { bd0, bd0, bd1, bd1 };   // n tile t=0
        float oa1[4] = { bd0, bd0, bd1, bd1 };   // n tile t=1

        #pragma unroll
        for (int k3 = 0; k3 < 3; k3++) {
            // stage-1: Z^T rows o(oc), both n'-halves
            float dA0 = 0.f, dA1 = 0.f, dA2 = 0.f, dA3 = 0.f;
            float dB0 = 0.f, dB1 = 0.f, dB2 = 0.f, dB3 = 0.f;
            #pragma unroll
            for (int ks = 0; ks < 4; ks++) {
                mma16816(dA0, dA1, dA2, dA3, wf[k3 * 4 + ks], bh[0][ks]);
                mma16816(dB0, dB1, dB2, dB3, wf[k3 * 4 + ks], bh[1][ks]);
            }
            // assemble stage-2 A-frag (m=o,k=s): k 0..7 from t=0, 8..15 from t=1
            uint4 za = make_uint4(pk16(dA0, dA1), pk16(dA2, dA3),
                                  pk16(dB0, dB1), pk16(dB2, dB3));

            // G fragments for both n-halves
            uint2 gh[2], gl[2];
            #pragma unroll
            for (int t = 0; t < 2; t++) {
                int ci = site * 48 + k3 * 16 + t * 8 + g;
                float w0v = CBW0[ci], w1v = CBW1[ci];
                int s01 = CBS[ci];
                int s0v = s01 >> 4, s1v = s01 & 15;
                float gv[4];
                #pragma unroll
                for (int i = 0; i < 4; i++) {
                    int s = q * 2 + (i & 1) + ((i >> 1) << 3);
                    gv[i] = ((s == s0v) ? w0v : 0.f) + ((s == s1v) ? w1v : 0.f);
                }
                uint32_t h01 = pk16(gv[0], gv[1]);
                uint32_t h23 = pk16(gv[2], gv[3]);
                float2 f01 = h2f2(h01);
                float2 f23 = h2f2(h23);
                gh[t] = make_uint2(h01, h23);
                gl[t] = make_uint2(pk16(gv[0] - f01.x, gv[1] - f01.y),
                                   pk16(gv[2] - f23.x, gv[3] - f23.y));
            }
            mma16816(oa0[0], oa0[1], oa0[2], oa0[3], za, gh[0]);
            mma16816(oa0[0], oa0[1], oa0[2], oa0[3], za, gl[0]);
            mma16816(oa1[0], oa1[1], oa1[2], oa1[3], za, gh[1]);
            mma16816(oa1[0], oa1[1], oa1[2], oa1[3], za, gl[1]);
        }

        // stash this site's outputs (swizzled)
        #pragma unroll
        for (int r = 0; r < 4; r++) {
            int o = oc * 16 + g + ((r >> 1) << 3);
            int n0 = 2 * q + (r & 1);
            int ph0 = (o & 7) | (((n0 >> 1) & 1) << 3);
            STG2[(o * 16 + n0) * 16 + (site ^ ph0)] = (r & 1) ? ((r >> 1) ? oa0[3] : oa0[1])
                                                              : ((r >> 1) ? oa0[2] : oa0[0]);
            int n1 = 8 + n0;
            int ph1 = (o & 7) | (((n1 >> 1) & 1) << 3);
            STG2[(o * 16 + n1) * 16 + (site ^ ph1)] = (r & 1) ? ((r >> 1) ? oa1[3] : oa1[1])
                                                              : ((r >> 1) ? oa1[2] : oa1[0]);
        }
    }

    // ---------------- coalesced store ----------------
    __syncthreads();
    {
        float* ob = out + xbase;
        #pragma unroll 8
        for (int idx = tid; idx < 16384; idx += 512) {
            int s = idx & 15, on = idx >> 4;
            int o = on >> 4, nn2 = on & 15;
            int ph = (o & 7) | (((nn2 >> 1) & 1) << 3);
            ob[(long)on * HW + s] = STG2[on * 16 + (s ^ ph)];
        }
    }
}

extern "C" void kernel_launch(void* const* d_in, const int* in_sizes, int n_in,
                              void* d_out, int out_size)
{
    const float* x     = (const float*)d_in[0];
    const float* w_off = (const float*)d_in[1];
    const float* b_off = (const float*)d_in[2];
    const float* w_def = (const float*)d_in[3];
    const float* b_def = (const float*)d_in[4];
    float* out = (float*)d_out;

    cudaFuncSetAttribute(deform_hmma10_kernel,
                         cudaFuncAttributeMaxDynamicSharedMemorySize, SMEM_TOTAL);

    // prep: build weight fragments once
    deform_prep_kernel<<<7, 256>>>(w_off, w_def);
    // main: 2 (B) * 96 (H) * 6 (W/16) = 1152 CTAs, 512 threads
    deform_hmma10_kernel<<<1152, 512, SMEM_TOTAL>>>(x, b_off, b_def, out);
}

// round 14
// speedup vs baseline: 1.1780x; 1.1780x over previous
#include <cuda_runtime.h>
#include <cuda_fp16.h>
#include <cstdint>

// DeformableFusionAcrossFocus R13: R10 structure (best: 90.6us) + two surgical cuts:
//   (1) G single fp16 (drop Gl pass): -24 MMAs/warp, halves stage-2 oa chain depth.
//   (2) stage-1 accumulator chains split 4-deep -> 2x2-deep (FADD join).
// Stage 1 (per site-warp): Z^T[m,n'] = sum_c W[m,c] * X[c,n']   (A=weights fp16, B=X fp16)
// Stage 2: out[o,n] += Z^T[o,s] * G[s,n],  G = interp matrix fp16.

#define HW 9216
#define NWF 1792     // 14 oc-groups * 4 ks * 32 lanes

// ---- smem byte layout ----
#define SM_WF    0        // weight A-frags [oc14][ks4][lane32] uint4 = 28672
#define SM_SCR   28672    // X staging 17664 floats = 70656B; reused as STG2 (16384 floats)
#define SM_ZOFF  99328    // per-warp offset buffer: 16 * 384 floats = 24576B
#define SM_BD    123904   // 64 floats
#define SM_BO    124160   // 6 floats (+pad)
#define SMEM_TOTAL 124192

__device__ uint4 g_WF[NWF];

__device__ __forceinline__ void mma16816(float& d0, float& d1, float& d2, float& d3,
                                         uint4 a, uint2 b) {
    asm volatile(
        "mma.sync.aligned.m16n8k16.row.col.f32.f16.f16.f32 "
        "{%0,%1,%2,%3}, {%4,%5,%6,%7}, {%8,%9}, {%0,%1,%2,%3};"
        : "+f"(d0), "+f"(d1), "+f"(d2), "+f"(d3)
        : "r"(a.x), "r"(a.y), "r"(a.z), "r"(a.w), "r"(b.x), "r"(b.y));
}

// pack two f32 -> f16x2 {lo=vlo, hi=vhi}
__device__ __forceinline__ uint32_t pk16(float vlo, float vhi) {
    uint32_t r;
    asm("cvt.rn.f16x2.f32 %0, %1, %2;" : "=r"(r) : "f"(vhi), "f"(vlo));
    return r;
}

__device__ __forceinline__ float wval(int m, int c,
                                      const float* __restrict__ w_def,
                                      const float* __restrict__ w_off) {
    if (m < 192) { int kk = m >> 6, o = m & 63; return __ldg(w_def + o * 192 + c * 3 + kk); }
    if (m < 210) { int t = m - 192; int kk = t / 6, j = t - 6 * kk;
                   return __ldg(w_off + j * 192 + c * 3 + kk); }
    return 0.f;
}

// ---------------- prep: build weight A-fragments once ----------------
__global__ void deform_prep_kernel(const float* __restrict__ w_off,
                                   const float* __restrict__ w_def)
{
    int idx = blockIdx.x * blockDim.x + threadIdx.x;
    if (idx >= NWF) return;
    int l = idx & 31, rem = idx >> 5;
    int ks = rem & 3, oc = rem >> 2;
    int qq = l & 3, gg = l >> 2;
    int c0 = ks * 16 + qq * 2;
    int m0 = oc * 16 + gg, m1 = m0 + 8;
    uint32_t a0 = pk16(wval(m0, c0,     w_def, w_off), wval(m0, c0 + 1, w_def, w_off));
    uint32_t a1 = pk16(wval(m1, c0,     w_def, w_off), wval(m1, c0 + 1, w_def, w_off));
    uint32_t a2 = pk16(wval(m0, c0 + 8, w_def, w_off), wval(m0, c0 + 9, w_def, w_off));
    uint32_t a3 = pk16(wval(m1, c0 + 8, w_def, w_off), wval(m1, c0 + 9, w_def, w_off));
    g_WF[(oc * 4 + ks) * 32 + l] = make_uint4(a0, a1, a2, a3);
}

__global__ void __launch_bounds__(512, 1)
deform_hmma11_kernel(const float* __restrict__ x,
                     const float* __restrict__ b_off,
                     const float* __restrict__ b_def,
                     float* __restrict__ out)
{
    extern __shared__ char smem[];
    uint4*  WF  = (uint4*)(smem + SM_WF);
    float*  SCR = (float*)(smem + SM_SCR);
    float*  ZOF = (float*)(smem + SM_ZOFF);
    float*  BD  = (float*)(smem + SM_BD);
    float*  BO  = (float*)(smem + SM_BO);

    const int tid  = threadIdx.x;
    const int wid  = tid >> 5;        // warp = local site (0..15)
    const int lane = tid & 31;
    const int g    = lane >> 2;       // fragment row group
    const int q    = lane & 3;        // fragment col group

    const int bid = blockIdx.x;       // 0..1151
    const int b   = bid / 576;
    const int h   = (bid / 6) % 96;
    const int w0  = (bid % 6) * 16;
    const long xbase = (long)b * (64 * 16 * HW) + (long)h * 96 + w0;

    if (tid < 64) BD[tid] = b_def[tid];
    if (tid < 6)  BO[tid] = b_off[tid];

    // ---------------- stage X[c][s][n] -> SCR[c*276 + s*17 + n] ----------------
    {
        const float* xb = x + xbase;
        #pragma unroll 8
        for (int i = tid; i < 16384; i += 512) {
            int s = i & 15, n = (i >> 4) & 15, c = i >> 8;
            SCR[c * 276 + s * 17 + n] = xb[(long)(c * 16 + n) * HW + s];
        }
    }

    // ---------------- weight A-fragments: coalesced copy from prebuilt buffer ----------------
    #pragma unroll 4
    for (int i = tid; i < NWF; i += 512)
        WF[i] = g_WF[i];
    __syncthreads();

    // ---------------- X B-fragments -> registers (single fp16) ----------------
    uint2 bh[2][4];
    {
        const float* base = SCR + wid * 17;
        #pragma unroll
        for (int t = 0; t < 2; t++) {
            const int nn = t * 8 + g;
            #pragma unroll
            for (int ks = 0; ks < 4; ks++) {
                int c0 = ks * 16 + q * 2;
                float v0 = base[(c0    ) * 276 + nn];
                float v1 = base[(c0 + 1) * 276 + nn];
                float v2 = base[(c0 + 8) * 276 + nn];
                float v3 = base[(c0 + 9) * 276 + nn];
                bh[t][ks] = make_uint2(pk16(v0, v1), pk16(v2, v3));
            }
        }
    }

    // ---------------- offsets: stage-1 on oc 12,13, stash to ZOF ----------------
    float* zoff = ZOF + wid * 384;    // rows 0..17, stride 20
    #pragma unroll
    for (int oo = 0; oo < 2; oo++) {
        const int ocg = 12 + oo;
        uint4 au[4];
        #pragma unroll
        for (int ks = 0; ks < 4; ks++) au[ks] = WF[(ocg * 4 + ks) * 32 + lane];
        float d00 = 0.f, d01 = 0.f, d02 = 0.f, d03 = 0.f;
        float d10 = 0.f, d11 = 0.f, d12 = 0.f, d13 = 0.f;
        #pragma unroll
        for (int ks = 0; ks < 4; ks++) {
            mma16816(d00, d01, d02, d03, au[ks], bh[0][ks]);
            mma16816(d10, d11, d12, d13, au[ks], bh[1][ks]);
        }
        int r0 = oo * 16 + g;
        if (r0 < 18) {
            *(float2*)(zoff + r0 * 20 + q * 2)     = make_float2(d00, d01);
            *(float2*)(zoff + r0 * 20 + q * 2 + 8) = make_float2(d10, d11);
        }
        int r1 = r0 + 8;
        if (r1 < 18) {
            *(float2*)(zoff + r1 * 20 + q * 2)     = make_float2(d02, d03);
            *(float2*)(zoff + r1 * 20 + q * 2 + 8) = make_float2(d12, d13);
        }
    }
    __syncwarp();

    // ---------------- interpolation coefficients (lane owns n = lane&15) ----------------
    const int n = lane & 15;
    float W0c[3], W1c[3];
    int   s0c[3], s1c[3];
    {
        float offv[6];
        #pragma unroll
        for (int j = 0; j < 6; j++) {
            float v = BO[j];
            #pragma unroll
            for (int kk = 0; kk < 3; kk++) {
                int np = n - 1 + kk;
                if (np >= 0 && np < 16)
                    v += zoff[(kk * 6 + j) * 20 + np];
            }
            offv[j] = v;
        }
        #pragma unroll
        for (int k = 0; k < 3; k++) {
            float px  = (float)(n - 1 + k) + offv[2 * k + 1];
            float x0f = floorf(px);
            float fx  = px - x0f;
            int x0i = (int)x0f, x1i = x0i + 1;
            float wy = fmaxf(0.f, 1.f - fabsf(offv[2 * k]));
            W0c[k] = (x0i >= 0 && x0i < 16) ? (1.f - fx) * wy : 0.f;
            W1c[k] = (x1i >= 0 && x1i < 16) ? fx * wy : 0.f;
            s0c[k] = min(max(x0i, 0), 15);
            s1c[k] = min(max(x1i, 0), 15);
        }
    }

    // ---------------- output accumulators: out[o = oc*16+g(+8)][n = t*8+2q(+1)] ----------------
    float oa[4][2][4];
    #pragma unroll
    for (int oc = 0; oc < 4; oc++) {
        float bd0 = BD[oc * 16 + g];
        float bd1 = BD[oc * 16 + g + 8];
        #pragma unroll
        for (int t = 0; t < 2; t++) {
            oa[oc][t][0] = bd0; oa[oc][t][1] = bd0;
            oa[oc][t][2] = bd1; oa[oc][t][3] = bd1;
        }
    }

    // ---------------- main: per k, stage-1 GEMM + stage-2 gather-MMA ----------------
    #pragma unroll
    for (int k3 = 0; k3 < 3; k3++) {
        // build G B-frags: G[s][n] = W0(n)*(s==s0(n)) + W1(n)*(s==s1(n)), single fp16
        uint2 gh[2];
        #pragma unroll
        for (int t = 0; t < 2; t++) {
            int nn = t * 8 + g;
            float w0v = __shfl_sync(0xffffffffu, W0c[k3], nn);
            float w1v = __shfl_sync(0xffffffffu, W1c[k3], nn);
            int   s0v = __shfl_sync(0xffffffffu, s0c[k3], nn);
            int   s1v = __shfl_sync(0xffffffffu, s1c[k3], nn);
            float gv[4];
            #pragma unroll
            for (int i = 0; i < 4; i++) {
                int s = q * 2 + (i & 1) + (i >> 1) * 8;
                gv[i] = ((s == s0v) ? w0v : 0.f) + ((s == s1v) ? w1v : 0.f);
            }
            gh[t] = make_uint2(pk16(gv[0], gv[1]), pk16(gv[2], gv[3]));
        }

        #pragma unroll
        for (int oc = 0; oc < 4; oc++) {
            const int ocg = k3 * 4 + oc;
            uint4 au[4];
            #pragma unroll
            for (int ks = 0; ks < 4; ks++) au[ks] = WF[(ocg * 4 + ks) * 32 + lane];
            // stage-1: two 2-deep chains per n-half (was one 4-deep chain)
            float d00 = 0.f, d01 = 0.f, d02 = 0.f, d03 = 0.f;
            float e00 = 0.f, e01 = 0.f, e02 = 0.f, e03 = 0.f;
            float d10 = 0.f, d11 = 0.f, d12 = 0.f, d13 = 0.f;
            float e10 = 0.f, e11 = 0.f, e12 = 0.f, e13 = 0.f;
            mma16816(d00, d01, d02, d03, au[0], bh[0][0]);
            mma16816(d10, d11, d12, d13, au[0], bh[1][0]);
            mma16816(e00, e01, e02, e03, au[2], bh[0][2]);
            mma16816(e10, e11, e12, e13, au[2], bh[1][2]);
            mma16816(d00, d01, d02, d03, au[1], bh[0][1]);
            mma16816(d10, d11, d12, d13, au[1], bh[1][1]);
            mma16816(e00, e01, e02, e03, au[3], bh[0][3]);
            mma16816(e10, e11, e12, e13, au[3], bh[1][3]);
            // Z^T D-frag -> stage-2 A-frag (fp16)
            uint4 za = make_uint4(pk16(d00 + e00, d01 + e01), pk16(d02 + e02, d03 + e03),
                                  pk16(d10 + e10, d11 + e11), pk16(d12 + e12, d13 + e13));
            mma16816(oa[oc][0][0], oa[oc][0][1], oa[oc][0][2], oa[oc][0][3], za, gh[0]);
            mma16816(oa[oc][1][0], oa[oc][1][1], oa[oc][1][2], oa[oc][1][3], za, gh[1]);
        }
    }

    // ---------------- staged coalesced store ----------------
    __syncthreads();   // everyone done with SCR (X staging) and ZOF
    {
        float* STG2 = SCR;
        #pragma unroll
        for (int oc = 0; oc < 4; oc++) {
            #pragma unroll
            for (int t = 0; t < 2; t++) {
                #pragma unroll
                for (int r = 0; r < 4; r++) {
                    int o  = oc * 16 + g + ((r >> 1) << 3);
                    int nn = t * 8 + 2 * q + (r & 1);
                    int ph = (o & 7) | (((nn >> 1) & 1) << 3);
                    STG2[(o * 16 + nn) * 16 + (wid ^ ph)] = oa[oc][t][r];
                }
            }
        }
    }
    __syncthreads();
    {
        const float* STG2 = SCR;
        float* ob = out + xbase;
        #pragma unroll 8
        for (int idx = tid; idx < 16384; idx += 512) {
            int s = idx & 15, on = idx >> 4;
            int o = on >> 4, nn = on & 15;
            int ph = (o & 7) | (((nn >> 1) & 1) << 3);
            ob[(long)on * HW + s] = STG2[on * 16 + (s ^ ph)];
        }
    }
}

extern "C" void kernel_launch(void* const* d_in, const int* in_sizes, int n_in,
                              void* d_out, int out_size)
{
    const float* x     = (const float*)d_in[0];
    const float* w_off = (const float*)d_in[1];
    const float* b_off = (const float*)d_in[2];
    const float* w_def = (const float*)d_in[3];
    const float* b_def = (const float*)d_in[4];
    float* out = (float*)d_out;

    cudaFuncSetAttribute(deform_hmma11_kernel,
                         cudaFuncAttributeMaxDynamicSharedMemorySize, SMEM_TOTAL);

    // prep: build weight fragments once
    deform_prep_kernel<<<7, 256>>>(w_off, w_def);
    // main: 2 (B) * 96 (H) * 6 (W/16) = 1152 CTAs, 512 threads
    deform_hmma11_kernel<<<1152, 512, SMEM_TOTAL>>>(x, b_off, b_def, out);
}

// round 16
// speedup vs baseline: 1.3022x; 1.1054x over previous
#include <cuda_runtime.h>
#include <cuda_fp16.h>
#include <cstdint>

// DeformableFusionAcrossFocus R14: R13 per-warp pipeline, repartitioned as
// 256-thread / 8-site CTAs with __launch_bounds__(256,2) -> 2 CTAs/SM
// (128 regs x 256 thr x 2 = full RF). Cross-CTA overlap of barriers and
// memory phases. Numerics identical to R13 (rel_err 6.37e-4).

#define HW 9216
#define NWF 1792     // 14 oc-groups * 4 ks * 32 lanes

// ---- smem byte layout (per 8-site CTA) ----
#define SM_WF    0        // weight A-frags = 28672
#define SM_SCR   28672    // X staging 64*140*4 = 35840; reused: STG2 (32768) after X dead
#define SM_ZOF   61440    // 8 warps * 384 floats = 12288 (overlaps X tail; written post-sync)
#define SM_BD    73728    // 64 floats
#define SM_BO    73984    // 6 floats (+pad)
#define SMEM_TOTAL 74016

__device__ uint4 g_WF[NWF];

__device__ __forceinline__ void mma16816(float& d0, float& d1, float& d2, float& d3,
                                         uint4 a, uint2 b) {
    asm volatile(
        "mma.sync.aligned.m16n8k16.row.col.f32.f16.f16.f32 "
        "{%0,%1,%2,%3}, {%4,%5,%6,%7}, {%8,%9}, {%0,%1,%2,%3};"
        : "+f"(d0), "+f"(d1), "+f"(d2), "+f"(d3)
        : "r"(a.x), "r"(a.y), "r"(a.z), "r"(a.w), "r"(b.x), "r"(b.y));
}

// pack two f32 -> f16x2 {lo=vlo, hi=vhi}
__device__ __forceinline__ uint32_t pk16(float vlo, float vhi) {
    uint32_t r;
    asm("cvt.rn.f16x2.f32 %0, %1, %2;" : "=r"(r) : "f"(vhi), "f"(vlo));
    return r;
}

__device__ __forceinline__ float wval(int m, int c,
                                      const float* __restrict__ w_def,
                                      const float* __restrict__ w_off) {
    if (m < 192) { int kk = m >> 6, o = m & 63; return __ldg(w_def + o * 192 + c * 3 + kk); }
    if (m < 210) { int t = m - 192; int kk = t / 6, j = t - 6 * kk;
                   return __ldg(w_off + j * 192 + c * 3 + kk); }
    return 0.f;
}

// ---------------- prep: build weight A-fragments once ----------------
__global__ void deform_prep_kernel(const float* __restrict__ w_off,
                                   const float* __restrict__ w_def)
{
    int idx = blockIdx.x * blockDim.x + threadIdx.x;
    if (idx >= NWF) return;
    int l = idx & 31, rem = idx >> 5;
    int ks = rem & 3, oc = rem >> 2;
    int qq = l & 3, gg = l >> 2;
    int c0 = ks * 16 + qq * 2;
    int m0 = oc * 16 + gg, m1 = m0 + 8;
    uint32_t a0 = pk16(wval(m0, c0,     w_def, w_off), wval(m0, c0 + 1, w_def, w_off));
    uint32_t a1 = pk16(wval(m1, c0,     w_def, w_off), wval(m1, c0 + 1, w_def, w_off));
    uint32_t a2 = pk16(wval(m0, c0 + 8, w_def, w_off), wval(m0, c0 + 9, w_def, w_off));
    uint32_t a3 = pk16(wval(m1, c0 + 8, w_def, w_off), wval(m1, c0 + 9, w_def, w_off));
    g_WF[(oc * 4 + ks) * 32 + l] = make_uint4(a0, a1, a2, a3);
}

__global__ void __launch_bounds__(256, 2)
deform_hmma12_kernel(const float* __restrict__ x,
                     const float* __restrict__ b_off,
                     const float* __restrict__ b_def,
                     float* __restrict__ out)
{
    extern __shared__ char smem[];
    uint4*  WF  = (uint4*)(smem + SM_WF);
    float*  SCR = (float*)(smem + SM_SCR);
    float*  ZOF = (float*)(smem + SM_ZOF);
    float*  BD  = (float*)(smem + SM_BD);
    float*  BO  = (float*)(smem + SM_BO);

    const int tid  = threadIdx.x;
    const int wid  = tid >> 5;        // warp = local site (0..7)
    const int lane = tid & 31;
    const int g    = lane >> 2;       // fragment row group
    const int q    = lane & 3;        // fragment col group

    const int bid = blockIdx.x;       // 0..2303
    const int b   = bid / 1152;
    const int h   = (bid / 12) % 96;
    const int w0  = (bid % 12) * 8;
    const long xbase = (long)b * (64 * 16 * HW) + (long)h * 96 + w0;

    if (tid < 64) BD[tid] = b_def[tid];
    if (tid < 6)  BO[tid] = b_off[tid];

    // ---------------- stage X[c][s][n] -> SCR[c*140 + s*17 + n] ----------------
    {
        const float* xb = x + xbase;
        #pragma unroll 8
        for (int i = tid; i < 8192; i += 256) {
            int s = i & 7, n = (i >> 3) & 15, c = i >> 7;
            SCR[c * 140 + s * 17 + n] = xb[(long)(c * 16 + n) * HW + s];
        }
    }

    // ---------------- weight A-fragments: coalesced copy from prebuilt buffer ----------------
    #pragma unroll 7
    for (int i = tid; i < NWF; i += 256)
        WF[i] = g_WF[i];
    __syncthreads();

    // ---------------- X B-fragments -> registers (single fp16) ----------------
    uint2 bh[2][4];
    {
        const float* base = SCR + wid * 17;
        #pragma unroll
        for (int t = 0; t < 2; t++) {
            const int nn = t * 8 + g;
            #pragma unroll
            for (int ks = 0; ks < 4; ks++) {
                int c0 = ks * 16 + q * 2;
                float v0 = base[(c0    ) * 140 + nn];
                float v1 = base[(c0 + 1) * 140 + nn];
                float v2 = base[(c0 + 8) * 140 + nn];
                float v3 = base[(c0 + 9) * 140 + nn];
                bh[t][ks] = make_uint2(pk16(v0, v1), pk16(v2, v3));
            }
        }
    }
    __syncthreads();   // X staging dead -> SCR reusable (STG2), ZOF tail writable

    // ---------------- offsets: stage-1 on oc 12,13, stash to ZOF ----------------
    float* zoff = ZOF + wid * 384;    // rows 0..17, stride 20
    #pragma unroll
    for (int oo = 0; oo < 2; oo++) {
        const int ocg = 12 + oo;
        uint4 au[4];
        #pragma unroll
        for (int ks = 0; ks < 4; ks++) au[ks] = WF[(ocg * 4 + ks) * 32 + lane];
        float d00 = 0.f, d01 = 0.f, d02 = 0.f, d03 = 0.f;
        float d10 = 0.f, d11 = 0.f, d12 = 0.f, d13 = 0.f;
        #pragma unroll
        for (int ks = 0; ks < 4; ks++) {
            mma16816(d00, d01, d02, d03, au[ks], bh[0][ks]);
            mma16816(d10, d11, d12, d13, au[ks], bh[1][ks]);
        }
        int r0 = oo * 16 + g;
        if (r0 < 18) {
            *(float2*)(zoff + r0 * 20 + q * 2)     = make_float2(d00, d01);
            *(float2*)(zoff + r0 * 20 + q * 2 + 8) = make_float2(d10, d11);
        }
        int r1 = r0 + 8;
        if (r1 < 18) {
            *(float2*)(zoff + r1 * 20 + q * 2)     = make_float2(d02, d03);
            *(float2*)(zoff + r1 * 20 + q * 2 + 8) = make_float2(d12, d13);
        }
    }
    __syncwarp();

    // ---------------- interpolation coefficients (lane owns n = lane&15) ----------------
    const int n = lane & 15;
    float W0c[3], W1c[3];
    int   s0c[3], s1c[3];
    {
        float offv[6];
        #pragma unroll
        for (int j = 0; j < 6; j++) {
            float v = BO[j];
            #pragma unroll
            for (int kk = 0; kk < 3; kk++) {
                int np = n - 1 + kk;
                if (np >= 0 && np < 16)
                    v += zoff[(kk * 6 + j) * 20 + np];
            }
            offv[j] = v;
        }
        #pragma unroll
        for (int k = 0; k < 3; k++) {
            float px  = (float)(n - 1 + k) + offv[2 * k + 1];
            float x0f = floorf(px);
            float fx  = px - x0f;
            int x0i = (int)x0f, x1i = x0i + 1;
            float wy = fmaxf(0.f, 1.f - fabsf(offv[2 * k]));
            W0c[k] = (x0i >= 0 && x0i < 16) ? (1.f - fx) * wy : 0.f;
            W1c[k] = (x1i >= 0 && x1i < 16) ? fx * wy : 0.f;
            s0c[k] = min(max(x0i, 0), 15);
            s1c[k] = min(max(x1i, 0), 15);
        }
    }

    // ---------------- output accumulators: out[o = oc*16+g(+8)][n = t*8+2q(+1)] ----------------
    float oa[4][2][4];
    #pragma unroll
    for (int oc = 0; oc < 4; oc++) {
        float bd0 = BD[oc * 16 + g];
        float bd1 = BD[oc * 16 + g + 8];
        #pragma unroll
        for (int t = 0; t < 2; t++) {
            oa[oc][t][0] = bd0; oa[oc][t][1] = bd0;
            oa[oc][t][2] = bd1; oa[oc][t][3] = bd1;
        }
    }

    // ---------------- main: per k, stage-1 GEMM + stage-2 gather-MMA ----------------
    #pragma unroll
    for (int k3 = 0; k3 < 3; k3++) {
        // G B-frags: G[s][n] = W0(n)*(s==s0(n)) + W1(n)*(s==s1(n)), single fp16
        uint2 gh[2];
        #pragma unroll
        for (int t = 0; t < 2; t++) {
            int nn = t * 8 + g;
            float w0v = __shfl_sync(0xffffffffu, W0c[k3], nn);
            float w1v = __shfl_sync(0xffffffffu, W1c[k3], nn);
            int   s0v = __shfl_sync(0xffffffffu, s0c[k3], nn);
            int   s1v = __shfl_sync(0xffffffffu, s1c[k3], nn);
            float gv[4];
            #pragma unroll
            for (int i = 0; i < 4; i++) {
                int s = q * 2 + (i & 1) + (i >> 1) * 8;
                gv[i] = ((s == s0v) ? w0v : 0.f) + ((s == s1v) ? w1v : 0.f);
            }
            gh[t] = make_uint2(pk16(gv[0], gv[1]), pk16(gv[2], gv[3]));
        }

        #pragma unroll
        for (int oc = 0; oc < 4; oc++) {
            const int ocg = k3 * 4 + oc;
            uint4 au[4];
            #pragma unroll
            for (int ks = 0; ks < 4; ks++) au[ks] = WF[(ocg * 4 + ks) * 32 + lane];
            // stage-1: two 2-deep chains per n-half
            float d00 = 0.f, d01 = 0.f, d02 = 0.f, d03 = 0.f;
            float e00 = 0.f, e01 = 0.f, e02 = 0.f, e03 = 0.f;
            float d10 = 0.f, d11 = 0.f, d12 = 0.f, d13 = 0.f;
            float e10 = 0.f, e11 = 0.f, e12 = 0.f, e13 = 0.f;
            mma16816(d00, d01, d02, d03, au[0], bh[0][0]);
            mma16816(d10, d11, d12, d13, au[0], bh[1][0]);
            mma16816(e00, e01, e02, e03, au[2], bh[0][2]);
            mma16816(e10, e11, e12, e13, au[2], bh[1][2]);
            mma16816(d00, d01, d02, d03, au[1], bh[0][1]);
            mma16816(d10, d11, d12, d13, au[1], bh[1][1]);
            mma16816(e00, e01, e02, e03, au[3], bh[0][3]);
            mma16816(e10, e11, e12, e13, au[3], bh[1][3]);
            uint4 za = make_uint4(pk16(d00 + e00, d01 + e01), pk16(d02 + e02, d03 + e03),
                                  pk16(d10 + e10, d11 + e11), pk16(d12 + e12, d13 + e13));
            mma16816(oa[oc][0][0], oa[oc][0][1], oa[oc][0][2], oa[oc][0][3], za, gh[0]);
            mma16816(oa[oc][1][0], oa[oc][1][1], oa[oc][1][2], oa[oc][1][3], za, gh[1]);
        }
    }

    // ---------------- staged coalesced store (STG2 aliases dead X staging) ----------------
    {
        float* STG2 = SCR;
        #pragma unroll
        for (int oc = 0; oc < 4; oc++) {
            #pragma unroll
            for (int t = 0; t < 2; t++) {
                #pragma unroll
                for (int r = 0; r < 4; r++) {
                    int o  = oc * 16 + g + ((r >> 1) << 3);
                    int nn = t * 8 + 2 * q + (r & 1);
                    STG2[(o * 16 + nn) * 8 + (wid ^ (o & 7))] = oa[oc][t][r];
                }
            }
        }
    }
    __syncthreads();
    {
        const float* STG2 = SCR;
        float* ob = out + xbase;
        #pragma unroll 8
        for (int idx = tid; idx < 8192; idx += 256) {
            int s = idx & 7, on = idx >> 3;
            int o = on >> 4;
            ob[(long)on * HW + s] = STG2[on * 8 + (s ^ (o & 7))];
        }
    }
}

extern "C" void kernel_launch(void* const* d_in, const int* in_sizes, int n_in,
                              void* d_out, int out_size)
{
    const float* x     = (const float*)d_in[0];
    const float* w_off = (const float*)d_in[1];
    const float* b_off = (const float*)d_in[2];
    const float* w_def = (const float*)d_in[3];
    const float* b_def = (const float*)d_in[4];
    float* out = (float*)d_out;

    cudaFuncSetAttribute(deform_hmma12_kernel,
                         cudaFuncAttributeMaxDynamicSharedMemorySize, SMEM_TOTAL);

    // prep: build weight fragments once
    deform_prep_kernel<<<7, 256>>>(w_off, w_def);
    // main: 2 (B) * 96 (H) * 12 (W/8) = 2304 CTAs, 256 threads, 2 CTAs/SM
    deform_hmma12_kernel<<<2304, 256, SMEM_TOTAL>>>(x, b_off, b_def, out);
}

// round 17
// speedup vs baseline: 1.3579x; 1.0428x over previous
#include <cuda_runtime.h>
#include <cuda_fp16.h>
#include <cstdint>

// DeformableFusionAcrossFocus R15: 16-site / 256-thread CTAs, 2 sites per warp,
// 2 CTAs/SM. WF fragment loads amortized over 2 sites (halved per site);
// 64B-coalesced X staging + store. oc loop split in 2 passes to keep oa at 32 regs.
// Per-site numerics identical to R13/R14 (rel_err 6.37e-4).

#define HW 9216
#define NWF 1792     // 14 oc-groups * 4 ks * 32 lanes

// ---- smem byte layout (per CTA) ----
#define SM_WF    0        // weight A-frags = 28672
#define SM_SCR   28672    // X staging 17664 floats = 70656B; aliased: ZOF (24576) then STG2 (65536)
#define SM_BD    99328    // 64 floats
#define SM_BO    99584    // 6 floats (+pad)
#define SMEM_TOTAL 99616

__device__ uint4 g_WF[NWF];

__device__ __forceinline__ void mma16816(float& d0, float& d1, float& d2, float& d3,
                                         uint4 a, uint2 b) {
    asm volatile(
        "mma.sync.aligned.m16n8k16.row.col.f32.f16.f16.f32 "
        "{%0,%1,%2,%3}, {%4,%5,%6,%7}, {%8,%9}, {%0,%1,%2,%3};"
        : "+f"(d0), "+f"(d1), "+f"(d2), "+f"(d3)
        : "r"(a.x), "r"(a.y), "r"(a.z), "r"(a.w), "r"(b.x), "r"(b.y));
}

// pack two f32 -> f16x2 {lo=vlo, hi=vhi}
__device__ __forceinline__ uint32_t pk16(float vlo, float vhi) {
    uint32_t r;
    asm("cvt.rn.f16x2.f32 %0, %1, %2;" : "=r"(r) : "f"(vhi), "f"(vlo));
    return r;
}

__device__ __forceinline__ float wval(int m, int c,
                                      const float* __restrict__ w_def,
                                      const float* __restrict__ w_off) {
    if (m < 192) { int kk = m >> 6, o = m & 63; return __ldg(w_def + o * 192 + c * 3 + kk); }
    if (m < 210) { int t = m - 192; int kk = t / 6, j = t - 6 * kk;
                   return __ldg(w_off + j * 192 + c * 3 + kk); }
    return 0.f;
}

// ---------------- prep: build weight A-fragments once ----------------
__global__ void deform_prep_kernel(const float* __restrict__ w_off,
                                   const float* __restrict__ w_def)
{
    int idx = blockIdx.x * blockDim.x + threadIdx.x;
    if (idx >= NWF) return;
    int l = idx & 31, rem = idx >> 5;
    int ks = rem & 3, oc = rem >> 2;
    int qq = l & 3, gg = l >> 2;
    int c0 = ks * 16 + qq * 2;
    int m0 = oc * 16 + gg, m1 = m0 + 8;
    uint32_t a0 = pk16(wval(m0, c0,     w_def, w_off), wval(m0, c0 + 1, w_def, w_off));
    uint32_t a1 = pk16(wval(m1, c0,     w_def, w_off), wval(m1, c0 + 1, w_def, w_off));
    uint32_t a2 = pk16(wval(m0, c0 + 8, w_def, w_off), wval(m0, c0 + 9, w_def, w_off));
    uint32_t a3 = pk16(wval(m1, c0 + 8, w_def, w_off), wval(m1, c0 + 9, w_def, w_off));
    g_WF[(oc * 4 + ks) * 32 + l] = make_uint4(a0, a1, a2, a3);
}

__global__ void __launch_bounds__(256, 2)
deform_hmma13_kernel(const float* __restrict__ x,
                     const float* __restrict__ b_off,
                     const float* __restrict__ b_def,
                     float* __restrict__ out)
{
    extern __shared__ char smem[];
    uint4*  WF  = (uint4*)(smem + SM_WF);
    float*  SCR = (float*)(smem + SM_SCR);      // X staging; aliased ZOF / STG2
    float*  ZOF = SCR;                          // 16 sites * 384 floats (post-X)
    float*  BD  = (float*)(smem + SM_BD);
    float*  BO  = (float*)(smem + SM_BO);

    const int tid  = threadIdx.x;
    const int wid  = tid >> 5;        // warp owns sites 2w, 2w+1
    const int lane = tid & 31;
    const int g    = lane >> 2;       // fragment row group
    const int q    = lane & 3;        // fragment col group

    const int bid = blockIdx.x;       // 0..1151
    const int b   = bid / 576;
    const int h   = (bid / 6) % 96;
    const int w0  = (bid % 6) * 16;
    const long xbase = (long)b * (64 * 16 * HW) + (long)h * 96 + w0;

    if (tid < 64) BD[tid] = b_def[tid];
    if (tid < 6)  BO[tid] = b_off[tid];

    // ---------------- stage X[c][s][n] -> SCR[c*276 + s*17 + n] (64B segments) ----------------
    {
        const float* xb = x + xbase;
        #pragma unroll 8
        for (int i = tid; i < 16384; i += 256) {
            int s = i & 15, n = (i >> 4) & 15, c = i >> 8;
            SCR[c * 276 + s * 17 + n] = xb[(long)(c * 16 + n) * HW + s];
        }
    }
    // ---------------- weight A-fragments: coalesced copy from prebuilt buffer ----------------
    #pragma unroll 7
    for (int i = tid; i < NWF; i += 256)
        WF[i] = g_WF[i];
    __syncthreads();

    // ---------------- X B-fragments -> registers: 2 sites (single fp16) ----------------
    uint2 bh[2][2][4];                // [site-in-warp][t][ks]
    #pragma unroll
    for (int s4 = 0; s4 < 2; s4++) {
        const float* base = SCR + (2 * wid + s4) * 17;
        #pragma unroll
        for (int t = 0; t < 2; t++) {
            const int nn = t * 8 + g;
            #pragma unroll
            for (int ks = 0; ks < 4; ks++) {
                int c0 = ks * 16 + q * 2;
                float v0 = base[(c0    ) * 276 + nn];
                float v1 = base[(c0 + 1) * 276 + nn];
                float v2 = base[(c0 + 8) * 276 + nn];
                float v3 = base[(c0 + 9) * 276 + nn];
                bh[s4][t][ks] = make_uint2(pk16(v0, v1), pk16(v2, v3));
            }
        }
    }
    __syncthreads();   // X staging dead -> SCR reusable as ZOF / STG2

    // ---------------- offsets: stage-1 on oc 12,13 for both sites -> ZOF ----------------
    #pragma unroll
    for (int oo = 0; oo < 2; oo++) {
        const int ocg = 12 + oo;
        uint4 au[4];
        #pragma unroll
        for (int ks = 0; ks < 4; ks++) au[ks] = WF[(ocg * 4 + ks) * 32 + lane];
        #pragma unroll
        for (int s4 = 0; s4 < 2; s4++) {
            float* zoff = ZOF + (2 * wid + s4) * 384;   // rows 0..17, stride 20
            float d00 = 0.f, d01 = 0.f, d02 = 0.f, d03 = 0.f;
            float d10 = 0.f, d11 = 0.f, d12 = 0.f, d13 = 0.f;
            #pragma unroll
            for (int ks = 0; ks < 4; ks++) {
                mma16816(d00, d01, d02, d03, au[ks], bh[s4][0][ks]);
                mma16816(d10, d11, d12, d13, au[ks], bh[s4][1][ks]);
            }
            int r0 = oo * 16 + g;
            if (r0 < 18) {
                *(float2*)(zoff + r0 * 20 + q * 2)     = make_float2(d00, d01);
                *(float2*)(zoff + r0 * 20 + q * 2 + 8) = make_float2(d10, d11);
            }
            int r1 = r0 + 8;
            if (r1 < 18) {
                *(float2*)(zoff + r1 * 20 + q * 2)     = make_float2(d02, d03);
                *(float2*)(zoff + r1 * 20 + q * 2 + 8) = make_float2(d12, d13);
            }
        }
    }
    __syncwarp();

    // ---------------- coefficients: lane = (st, n), st = lane>>4 ----------------
    const int n  = lane & 15;
    const int st = lane >> 4;
    float W0c[3], W1c[3];
    int   s0c[3], s1c[3];
    {
        const float* zf = ZOF + (2 * wid + st) * 384;
        float offv[6];
        #pragma unroll
        for (int j = 0; j < 6; j++) {
            float v = BO[j];
            #pragma unroll
            for (int kk = 0; kk < 3; kk++) {
                int np = n - 1 + kk;
                if (np >= 0 && np < 16)
                    v += zf[(kk * 6 + j) * 20 + np];
            }
            offv[j] = v;
        }
        #pragma unroll
        for (int k = 0; k < 3; k++) {
            float px  = (float)(n - 1 + k) + offv[2 * k + 1];
            float x0f = floorf(px);
            float fx  = px - x0f;
            int x0i = (int)x0f, x1i = x0i + 1;
            float wy = fmaxf(0.f, 1.f - fabsf(offv[2 * k]));
            W0c[k] = (x0i >= 0 && x0i < 16) ? (1.f - fx) * wy : 0.f;
            W1c[k] = (x1i >= 0 && x1i < 16) ? fx * wy : 0.f;
            s0c[k] = min(max(x0i, 0), 15);
            s1c[k] = min(max(x1i, 0), 15);
        }
    }
    __syncthreads();   // all coeff reads done; ZOF region free (STG2 may overwrite)

    float* STG2 = SCR;

    // ---------------- main: 2 passes over oc (pass p: oc = 2p, 2p+1) ----------------
    #pragma unroll 1
    for (int p = 0; p < 2; p++) {
        // accumulators for this pass: [site2][oc2][t2][4]
        float oa[2][2][2][4];
        #pragma unroll
        for (int s4 = 0; s4 < 2; s4++)
            #pragma unroll
            for (int oj = 0; oj < 2; oj++) {
                int oc = 2 * p + oj;
                float bd0 = BD[oc * 16 + g];
                float bd1 = BD[oc * 16 + g + 8];
                #pragma unroll
                for (int t = 0; t < 2; t++) {
                    oa[s4][oj][t][0] = bd0; oa[s4][oj][t][1] = bd0;
                    oa[s4][oj][t][2] = bd1; oa[s4][oj][t][3] = bd1;
                }
            }

        #pragma unroll
        for (int k3 = 0; k3 < 3; k3++) {
            // G B-frags for both sites, both halves (single fp16)
            uint2 gh[2][2];
            #pragma unroll
            for (int s4 = 0; s4 < 2; s4++)
                #pragma unroll
                for (int t = 0; t < 2; t++) {
                    int srcl = s4 * 16 + t * 8 + g;
                    float w0v = __shfl_sync(0xffffffffu, W0c[k3], srcl);
                    float w1v = __shfl_sync(0xffffffffu, W1c[k3], srcl);
                    int   s0v = __shfl_sync(0xffffffffu, s0c[k3], srcl);
                    int   s1v = __shfl_sync(0xffffffffu, s1c[k3], srcl);
                    float gv[4];
                    #pragma unroll
                    for (int i = 0; i < 4; i++) {
                        int s = q * 2 + (i & 1) + (i >> 1) * 8;
                        gv[i] = ((s == s0v) ? w0v : 0.f) + ((s == s1v) ? w1v : 0.f);
                    }
                    gh[s4][t] = make_uint2(pk16(gv[0], gv[1]), pk16(gv[2], gv[3]));
                }

            #pragma unroll
            for (int oj = 0; oj < 2; oj++) {
                const int ocg = k3 * 4 + 2 * p + oj;
                uint4 au[4];
                #pragma unroll
                for (int ks = 0; ks < 4; ks++) au[ks] = WF[(ocg * 4 + ks) * 32 + lane];
                #pragma unroll
                for (int s4 = 0; s4 < 2; s4++) {
                    // stage-1: two 2-deep chains per n-half (numerics = R13)
                    float d00 = 0.f, d01 = 0.f, d02 = 0.f, d03 = 0.f;
                    float e00 = 0.f, e01 = 0.f, e02 = 0.f, e03 = 0.f;
                    float d10 = 0.f, d11 = 0.f, d12 = 0.f, d13 = 0.f;
                    float e10 = 0.f, e11 = 0.f, e12 = 0.f, e13 = 0.f;
                    mma16816(d00, d01, d02, d03, au[0], bh[s4][0][0]);
                    mma16816(d10, d11, d12, d13, au[0], bh[s4][1][0]);
                    mma16816(e00, e01, e02, e03, au[2], bh[s4][0][2]);
                    mma16816(e10, e11, e12, e13, au[2], bh[s4][1][2]);
                    mma16816(d00, d01, d02, d03, au[1], bh[s4][0][1]);
                    mma16816(d10, d11, d12, d13, au[1], bh[s4][1][1]);
                    mma16816(e00, e01, e02, e03, au[3], bh[s4][0][3]);
                    mma16816(e10, e11, e12, e13, au[3], bh[s4][1][3]);
                    uint4 za = make_uint4(pk16(d00 + e00, d01 + e01),
                                          pk16(d02 + e02, d03 + e03),
                                          pk16(d10 + e10, d11 + e11),
                                          pk16(d12 + e12, d13 + e13));
                    mma16816(oa[s4][oj][0][0], oa[s4][oj][0][1],
                             oa[s4][oj][0][2], oa[s4][oj][0][3], za, gh[s4][0]);
                    mma16816(oa[s4][oj][1][0], oa[s4][oj][1][1],
                             oa[s4][oj][1][2], oa[s4][oj][1][3], za, gh[s4][1]);
                }
            }
        }

        // stash this pass's outputs (swizzled, R13 pattern)
        #pragma unroll
        for (int s4 = 0; s4 < 2; s4++) {
            const int site = 2 * wid + s4;
            #pragma unroll
            for (int oj = 0; oj < 2; oj++) {
                int oc = 2 * p + oj;
                #pragma unroll
                for (int t = 0; t < 2; t++) {
                    #pragma unroll
                    for (int r = 0; r < 4; r++) {
                        int o  = oc * 16 + g + ((r >> 1) << 3);
                        int nn = t * 8 + 2 * q + (r & 1);
                        int ph = (o & 7) | (((nn >> 1) & 1) << 3);
                        STG2[(o * 16 + nn) * 16 + (site ^ ph)] = oa[s4][oj][t][r];
                    }
                }
            }
        }
    }

    // ---------------- coalesced store ----------------
    __syncthreads();
    {
        float* ob = out + xbase;
        #pragma unroll 8
        for (int idx = tid; idx < 16384; idx += 256) {
            int s = idx & 15, on = idx >> 4;
            int o = on >> 4, nn = on & 15;
            int ph = (o & 7) | (((nn >> 1) & 1) << 3);
            ob[(long)on * HW + s] = STG2[on * 16 + (s ^ ph)];
        }
    }
}

extern "C" void kernel_launch(void* const* d_in, const int* in_sizes, int n_in,
                              void* d_out, int out_size)
{
    const float* x     = (const float*)d_in[0];
    const float* w_off = (const float*)d_in[1];
    const float* b_off = (const float*)d_in[2];
    const float* w_def = (const float*)d_in[3];
    const float* b_def = (const float*)d_in[4];
    float* out = (float*)d_out;

    cudaFuncSetAttribute(deform_hmma13_kernel,
                         cudaFuncAttributeMaxDynamicSharedMemorySize, SMEM_TOTAL);

    // prep: build weight fragments once
    deform_prep_kernel<<<7, 256>>>(w_off, w_def);
    // main: 2 (B) * 96 (H) * 6 (W/16) = 1152 CTAs, 256 threads, 2 CTAs/SM
    deform_hmma13_kernel<<<1152, 256, SMEM_TOTAL>>>(x, b_off, b_def, out);
}